// round 1
// baseline (speedup 1.0000x reference)
#include <cuda_runtime.h>
#include <math.h>

#define L_TOT 8500
#define DD 256
#define NH 8
#define NL 4
#define NP 4
#define DH 32
#define DFF 1024

// ---------------- scratch (static device allocations are allowed) ----------
__device__ float g_q[L_TOT * DD];        // src + pos
__device__ float g_off[L_TOT * DD];      // sampling offsets (NH*NL*NP*2 = 256)
__device__ float g_attn[L_TOT * 128];    // attention logits -> weights
__device__ float g_value[L_TOT * DD];    // src @ Wv + bv
__device__ float g_attnout[L_TOT * DD];  // deformable attention output
__device__ float g_x1[L_TOT * DD];       // after first LayerNorm
__device__ float g_h[L_TOT * DFF];       // FFN hidden
__device__ float g_tmp[L_TOT * DD];      // generic temp

// ---------------- elementwise add ----------------
__global__ void add_kernel(const float* __restrict__ a, const float* __restrict__ b,
                           float* __restrict__ c, int n) {
    int i = blockIdx.x * blockDim.x + threadIdx.x;
    if (i < n) c[i] = a[i] + b[i];
}

// ---------------- SGEMM: C[M,N] = A[M,K] @ W[K,N] + bias, optional ReLU -----
// BM=BN=64, BK=16, 256 threads, 4x4 per thread.
__global__ void sgemm_kernel(const float* __restrict__ A, const float* __restrict__ W,
                             const float* __restrict__ bias, float* __restrict__ C,
                             int M, int N, int K, int relu) {
    __shared__ float As[16][64];
    __shared__ float Bs[16][68];   // +4 pad to soften bank conflicts

    const int tid = threadIdx.x;
    const int tx = tid & 15;       // 0..15 (col group)
    const int ty = tid >> 4;       // 0..15 (row group)
    const int blockRow = blockIdx.y * 64;
    const int blockCol = blockIdx.x * 64;

    // A tile load mapping: 64 rows x 16 cols, float4 per thread
    const int arow = tid >> 2;          // 0..63
    const int acol = (tid & 3) * 4;     // 0,4,8,12
    // B tile load mapping: 16 rows x 64 cols, float4 per thread
    const int brow = tid >> 4;          // 0..15
    const int bcol = (tid & 15) * 4;    // 0..60

    float acc[4][4] = {};

    for (int k0 = 0; k0 < K; k0 += 16) {
        float4 av = make_float4(0.f, 0.f, 0.f, 0.f);
        int gr = blockRow + arow;
        if (gr < M)
            av = *reinterpret_cast<const float4*>(&A[(long)gr * K + k0 + acol]);
        As[acol + 0][arow] = av.x;
        As[acol + 1][arow] = av.y;
        As[acol + 2][arow] = av.z;
        As[acol + 3][arow] = av.w;

        float4 bv = *reinterpret_cast<const float4*>(&W[(long)(k0 + brow) * N + blockCol + bcol]);
        Bs[brow][bcol + 0] = bv.x;
        Bs[brow][bcol + 1] = bv.y;
        Bs[brow][bcol + 2] = bv.z;
        Bs[brow][bcol + 3] = bv.w;

        __syncthreads();

        #pragma unroll
        for (int kk = 0; kk < 16; ++kk) {
            float a[4], b[4];
            #pragma unroll
            for (int i = 0; i < 4; i++) a[i] = As[kk][ty * 4 + i];
            #pragma unroll
            for (int j = 0; j < 4; j++) b[j] = Bs[kk][tx * 4 + j];
            #pragma unroll
            for (int i = 0; i < 4; i++)
                #pragma unroll
                for (int j = 0; j < 4; j++)
                    acc[i][j] = fmaf(a[i], b[j], acc[i][j]);
        }
        __syncthreads();
    }

    #pragma unroll
    for (int i = 0; i < 4; i++) {
        int r = blockRow + ty * 4 + i;
        if (r >= M) continue;
        #pragma unroll
        for (int j = 0; j < 4; j++) {
            int c = blockCol + tx * 4 + j;
            float v = acc[i][j] + bias[c];
            if (relu) v = fmaxf(v, 0.f);
            C[(long)r * N + c] = v;
        }
    }
}

// ---------------- softmax over 16 (per l,h) in-place ----------------
__global__ void softmax16_kernel(float* __restrict__ a) {
    int idx = blockIdx.x * blockDim.x + threadIdx.x;
    if (idx >= L_TOT * NH) return;
    float* p = a + (long)idx * 16;
    float v[16];
    float m = -1e30f;
    #pragma unroll
    for (int i = 0; i < 16; i++) { v[i] = p[i]; m = fmaxf(m, v[i]); }
    float s = 0.f;
    #pragma unroll
    for (int i = 0; i < 16; i++) { v[i] = expf(v[i] - m); s += v[i]; }
    float inv = 1.f / s;
    #pragma unroll
    for (int i = 0; i < 16; i++) p[i] = v[i] * inv;
}

// ---------------- multi-scale deformable attention core ----------------
// one warp per (l, h); lane = channel dh (DH==32)
__global__ void msda_kernel(const float* __restrict__ value,
                            const float* __restrict__ off,
                            const float* __restrict__ attn,
                            const float* __restrict__ refpts,
                            float* __restrict__ out) {
    const int warp_in_block = threadIdx.x >> 5;
    const int lane = threadIdx.x & 31;
    const int l = blockIdx.x;
    const int h = warp_in_block;          // blockDim=256 -> 8 warps = NH
    if (l >= L_TOT) return;

    const int Hs[4] = {80, 40, 20, 10};
    const int Ws[4] = {80, 40, 20, 10};
    const int starts[4] = {0, 6400, 8000, 8400};

    float acc = 0.f;
    #pragma unroll
    for (int lvl = 0; lvl < NL; ++lvl) {
        const int Wl = Ws[lvl], Hl = Hs[lvl], st = starts[lvl];
        const float rx = refpts[((long)l * NL + lvl) * 2 + 0];
        const float ry = refpts[((long)l * NL + lvl) * 2 + 1];
        #pragma unroll
        for (int p = 0; p < NP; ++p) {
            const long oi = (long)l * DD + h * (NL * NP * 2) + lvl * (NP * 2) + p * 2;
            const float offx = off[oi];
            const float offy = off[oi + 1];
            // loc.x * Wl - 0.5 == rx*Wl + offx - 0.5 (normalizer = Wl)
            const float x = rx * Wl + offx - 0.5f;
            const float y = ry * Hl + offy - 0.5f;
            const float aw = attn[(long)l * 128 + h * 16 + lvl * 4 + p];
            const int x0 = (int)floorf(x);
            const int y0 = (int)floorf(y);
            const float fx = x - x0;
            const float fy = y - y0;
            float samp = 0.f;
            #pragma unroll
            for (int dy = 0; dy < 2; ++dy) {
                #pragma unroll
                for (int dx = 0; dx < 2; ++dx) {
                    const int xi = x0 + dx;
                    const int yi = y0 + dy;
                    if (xi >= 0 && xi < Wl && yi >= 0 && yi < Hl) {
                        const float w = (dx ? fx : 1.f - fx) * (dy ? fy : 1.f - fy);
                        const long vidx = (long)(st + yi * Wl + xi) * DD + h * DH + lane;
                        samp = fmaf(w, value[vidx], samp);
                    }
                }
            }
            acc = fmaf(aw, samp, acc);
        }
    }
    out[(long)l * DD + h * DH + lane] = acc;
}

// ---------------- fused residual add + LayerNorm (256 threads = 1 row) -----
__global__ void add_ln_kernel(const float* __restrict__ a, const float* __restrict__ b,
                              const float* __restrict__ g, const float* __restrict__ be,
                              float* __restrict__ out) {
    const int row = blockIdx.x;
    const int t = threadIdx.x;
    const float v = a[(long)row * DD + t] + b[(long)row * DD + t];

    float s = v, s2 = v * v;
    __shared__ float sh[8], sh2[8];
    #pragma unroll
    for (int o = 16; o > 0; o >>= 1) {
        s  += __shfl_down_sync(0xffffffffu, s, o);
        s2 += __shfl_down_sync(0xffffffffu, s2, o);
    }
    const int w = t >> 5, lane = t & 31;
    if (lane == 0) { sh[w] = s; sh2[w] = s2; }
    __syncthreads();
    if (w == 0) {
        s  = (lane < 8) ? sh[lane]  : 0.f;
        s2 = (lane < 8) ? sh2[lane] : 0.f;
        #pragma unroll
        for (int o = 4; o > 0; o >>= 1) {
            s  += __shfl_down_sync(0xffffffffu, s, o);
            s2 += __shfl_down_sync(0xffffffffu, s2, o);
        }
        if (lane == 0) { sh[0] = s; sh2[0] = s2; }
    }
    __syncthreads();
    const float mean = sh[0] * (1.f / DD);
    const float var  = sh2[0] * (1.f / DD) - mean * mean;
    const float inv  = rsqrtf(var + 1e-5f);
    out[(long)row * DD + t] = (v - mean) * inv * g[t] + be[t];
}

// ---------------- launch ----------------
extern "C" void kernel_launch(void* const* d_in, const int* in_sizes, int n_in,
                              void* d_out, int out_size) {
    const float* src  = (const float*)d_in[0];
    const float* pos  = (const float*)d_in[1];
    const float* refp = (const float*)d_in[2];
    // d_in[3] spatial_shapes, d_in[4] level_start_index, d_in[5] scale: hardcoded/unused
    const float* Wo   = (const float*)d_in[6];
    const float* bo   = (const float*)d_in[7];
    const float* Wa   = (const float*)d_in[8];
    const float* ba   = (const float*)d_in[9];
    const float* Wv   = (const float*)d_in[10];
    const float* bv   = (const float*)d_in[11];
    const float* Wout = (const float*)d_in[12];
    const float* bout = (const float*)d_in[13];
    const float* W1   = (const float*)d_in[14];
    const float* b1   = (const float*)d_in[15];
    const float* W2   = (const float*)d_in[16];
    const float* b2   = (const float*)d_in[17];
    const float* g1   = (const float*)d_in[18];
    const float* be1  = (const float*)d_in[19];
    const float* g2   = (const float*)d_in[20];
    const float* be2  = (const float*)d_in[21];
    float* out = (float*)d_out;

    float *q, *off, *attn, *value, *attnout, *x1, *h, *tmp;
    cudaGetSymbolAddress((void**)&q,       g_q);
    cudaGetSymbolAddress((void**)&off,     g_off);
    cudaGetSymbolAddress((void**)&attn,    g_attn);
    cudaGetSymbolAddress((void**)&value,   g_value);
    cudaGetSymbolAddress((void**)&attnout, g_attnout);
    cudaGetSymbolAddress((void**)&x1,      g_x1);
    cudaGetSymbolAddress((void**)&h,       g_h);
    cudaGetSymbolAddress((void**)&tmp,     g_tmp);

    const int M = L_TOT;
    const dim3 blk(256);
    const int gy = (M + 63) / 64;

    // 1) q = src + pos
    add_kernel<<<(M * DD + 255) / 256, blk>>>(src, pos, q, M * DD);

    // 2) off = q @ Wo + bo   (N=256, K=256)
    sgemm_kernel<<<dim3(4, gy), blk>>>(q, Wo, bo, off, M, 256, 256, 0);

    // 3) attn logits = q @ Wa + ba   (N=128, K=256)
    sgemm_kernel<<<dim3(2, gy), blk>>>(q, Wa, ba, attn, M, 128, 256, 0);

    // 4) softmax over 16 per (l,h)
    softmax16_kernel<<<(M * NH + 255) / 256, blk>>>(attn);

    // 5) value = src @ Wv + bv   (N=256, K=256)
    sgemm_kernel<<<dim3(4, gy), blk>>>(src, Wv, bv, value, M, 256, 256, 0);

    // 6) deformable attention sampling
    msda_kernel<<<M, blk>>>(value, off, attn, refp, attnout);

    // 7) src2 = attnout @ Wout + bout
    sgemm_kernel<<<dim3(4, gy), blk>>>(attnout, Wout, bout, tmp, M, 256, 256, 0);

    // 8) x1 = LN(src + src2)
    add_ln_kernel<<<M, blk>>>(src, tmp, g1, be1, x1);

    // 9) h = relu(x1 @ W1 + b1)   (N=1024, K=256)
    sgemm_kernel<<<dim3(16, gy), blk>>>(x1, W1, b1, h, M, 1024, 256, 1);

    // 10) tmp = h @ W2 + b2   (N=256, K=1024)
    sgemm_kernel<<<dim3(4, gy), blk>>>(h, W2, b2, tmp, M, 256, 1024, 0);

    // 11) out = LN(x1 + tmp)
    add_ln_kernel<<<M, blk>>>(x1, tmp, g2, be2, out);
}

// round 3
// speedup vs baseline: 2.0931x; 2.0931x over previous
#include <cuda_runtime.h>
#include <math.h>
#include <stdint.h>

#define L_TOT 8500
#define DD 256
#define NH 8
#define NL 4
#define NP 4
#define DH 32
#define DFF 1024

// ---------------- scratch ----------------
__device__ float g_q[L_TOT * DD];
__device__ float g_off[L_TOT * DD];
__device__ float g_attn[L_TOT * 128];
__device__ float g_value[L_TOT * DD];
__device__ float g_attnout[L_TOT * DD];
__device__ float g_x1[L_TOT * DD];
__device__ float g_h[L_TOT * DFF];
__device__ float g_tmp[L_TOT * DD];
// transposed weights [N, K]
__device__ float g_WoT[256 * 256];
__device__ float g_WaT[128 * 256];
__device__ float g_WvT[256 * 256];
__device__ float g_WoutT[256 * 256];
__device__ float g_W1T[1024 * 256];
__device__ float g_W2T[256 * 1024];

// ---------------- helpers ----------------
__device__ __forceinline__ uint32_t smem_u32(const void* p) {
    uint32_t a;
    asm("{ .reg .u64 t; cvta.to.shared.u64 t, %1; cvt.u32.u64 %0, t; }" : "=r"(a) : "l"(p));
    return a;
}
__device__ __forceinline__ uint32_t f2tf32(float x) {
    uint32_t r;
    asm("cvt.rna.tf32.f32 %0, %1;" : "=r"(r) : "f"(x));
    return r;
}
__device__ __forceinline__ void cp_async16(uint32_t sa, const void* ga) {
    asm volatile("cp.async.cg.shared.global [%0], [%1], 16;" :: "r"(sa), "l"(ga));
}
__device__ __forceinline__ void cp_commit() {
    asm volatile("cp.async.commit_group;" ::: "memory");
}
template <int N_>
__device__ __forceinline__ void cp_wait() {
    asm volatile("cp.async.wait_group %0;" :: "n"(N_) : "memory");
}
__device__ __forceinline__ void mma_tf32(float* c, const uint32_t* a, const uint32_t* b) {
    asm volatile(
        "mma.sync.aligned.m16n8k8.row.col.f32.tf32.tf32.f32 "
        "{%0,%1,%2,%3}, {%4,%5,%6,%7}, {%8,%9}, {%0,%1,%2,%3};"
        : "+f"(c[0]), "+f"(c[1]), "+f"(c[2]), "+f"(c[3])
        : "r"(a[0]), "r"(a[1]), "r"(a[2]), "r"(a[3]), "r"(b[0]), "r"(b[1]));
}

// ---------------- tf32 tensor-core GEMM (mma.sync path) ----------------
// C[M,N] = A[M,K] @ Bt[N,K]^T + bias.  Block tile 128x128, BK=32,
// 256 threads = 8 warps (2 x 4), warp tile 64x32 (4x4 m16n8k8 frags).
// Double-buffered cp.async pipeline.  SMEM row stride 36 floats.
#define SM_STRIDE 36
#define SM_TILE   (128 * SM_STRIDE)          // floats per tile
#define GEMM_SMEM_BYTES (4 * SM_TILE * 4)    // 2 stages x (A,B) = 73728 B

__global__ void __launch_bounds__(256) gemm_tf32_kernel(
    const float* __restrict__ A, const float* __restrict__ Bt,
    const float* __restrict__ bias, float* __restrict__ C,
    int M, int N, int K, int relu)
{
    extern __shared__ float sm[];
    float* AsBase = sm;                 // [2][SM_TILE]
    float* BsBase = sm + 2 * SM_TILE;   // [2][SM_TILE]
    const uint32_t smem_base = smem_u32(sm);

    const int tid = threadIdx.x;
    const int wid = tid >> 5;
    const int lane = tid & 31;
    const int warp_m = wid >> 2;        // 0..1
    const int warp_n = wid & 3;         // 0..3
    const int tr = lane >> 2;           // 0..7
    const int tc = lane & 3;            // 0..3
    const int blockRow = blockIdx.y * 128;
    const int blockCol = blockIdx.x * 128;

    float acc[4][4][4];
    #pragma unroll
    for (int i = 0; i < 4; i++)
        #pragma unroll
        for (int j = 0; j < 4; j++)
            #pragma unroll
            for (int r = 0; r < 4; r++) acc[i][j][r] = 0.f;

    // per-thread load mapping: 4 x 16B chunks for A, 4 for B, per stage
    const int lrow = tid >> 3;          // will add it*32
    const int lc4 = (tid & 7) * 4;

    const int NC = K >> 5;

    auto issue_stage = [&](int s, int k0) {
        const uint32_t a_base = smem_base + (uint32_t)(s * SM_TILE * 4);
        const uint32_t b_base = smem_base + (uint32_t)((2 + s) * SM_TILE * 4);
        #pragma unroll
        for (int it = 0; it < 4; ++it) {
            const int row = lrow + it * 32;
            int gr = blockRow + row;
            gr = gr < M - 1 ? gr : M - 1;
            const uint32_t so = (uint32_t)((row * SM_STRIDE + lc4) * 4);
            cp_async16(a_base + so, A + (size_t)gr * K + k0 + lc4);
            cp_async16(b_base + so, Bt + (size_t)(blockCol + row) * K + k0 + lc4);
        }
        cp_commit();
    };

    issue_stage(0, 0);
    issue_stage(1, 32);

    for (int i = 0; i < NC; ++i) {
        const int s = i & 1;
        cp_wait<1>();
        __syncthreads();

        const float* As = AsBase + s * SM_TILE;
        const float* Bs = BsBase + s * SM_TILE;
        const int amr = warp_m * 64;
        const int bnr = warp_n * 32;

        #pragma unroll
        for (int kb = 0; kb < 32; kb += 8) {
            uint32_t afr[4][4];
            #pragma unroll
            for (int im = 0; im < 4; ++im) {
                const int mr = amr + im * 16;
                const float* ap = As + (mr + tr) * SM_STRIDE + kb + tc;
                afr[im][0] = f2tf32(ap[0]);
                afr[im][1] = f2tf32(ap[8 * SM_STRIDE]);
                afr[im][2] = f2tf32(ap[4]);
                afr[im][3] = f2tf32(ap[8 * SM_STRIDE + 4]);
            }
            uint32_t bfr[4][2];
            #pragma unroll
            for (int in_ = 0; in_ < 4; ++in_) {
                const int nb = bnr + in_ * 8;
                const float* bp = Bs + (nb + tr) * SM_STRIDE + kb + tc;
                bfr[in_][0] = f2tf32(bp[0]);
                bfr[in_][1] = f2tf32(bp[4]);
            }
            #pragma unroll
            for (int im = 0; im < 4; ++im)
                #pragma unroll
                for (int in_ = 0; in_ < 4; ++in_)
                    mma_tf32(acc[im][in_], afr[im], bfr[in_]);
        }

        __syncthreads();
        if (i + 2 < NC) issue_stage(s, (i + 2) << 5);
    }

    // epilogue
    #pragma unroll
    for (int im = 0; im < 4; ++im) {
        const int row0 = blockRow + warp_m * 64 + im * 16 + tr;
        #pragma unroll
        for (int in_ = 0; in_ < 4; ++in_) {
            const int col = blockCol + warp_n * 32 + in_ * 8 + 2 * tc;
            const float bx = bias[col], by = bias[col + 1];
            float2 v0 = make_float2(acc[im][in_][0] + bx, acc[im][in_][1] + by);
            float2 v1 = make_float2(acc[im][in_][2] + bx, acc[im][in_][3] + by);
            if (relu) {
                v0.x = fmaxf(v0.x, 0.f); v0.y = fmaxf(v0.y, 0.f);
                v1.x = fmaxf(v1.x, 0.f); v1.y = fmaxf(v1.y, 0.f);
            }
            if (row0 < M)
                *reinterpret_cast<float2*>(C + (size_t)row0 * N + col) = v0;
            if (row0 + 8 < M)
                *reinterpret_cast<float2*>(C + (size_t)(row0 + 8) * N + col) = v1;
        }
    }
}

// ---------------- weight transpose: out[C,R] = in[R,C]^T ----------------
__global__ void transpose_kernel(const float* __restrict__ in, float* __restrict__ out,
                                 int R, int C) {
    __shared__ float tile[32][33];
    const int c0 = blockIdx.x * 32;
    const int r0 = blockIdx.y * 32;
    const int x = threadIdx.x;
    for (int yy = threadIdx.y; yy < 32; yy += 8)
        tile[yy][x] = in[(size_t)(r0 + yy) * C + c0 + x];
    __syncthreads();
    for (int yy = threadIdx.y; yy < 32; yy += 8)
        out[(size_t)(c0 + yy) * R + r0 + x] = tile[x][yy];
}

// ---------------- elementwise add ----------------
__global__ void add_kernel(const float* __restrict__ a, const float* __restrict__ b,
                           float* __restrict__ c, int n4) {
    int i = blockIdx.x * blockDim.x + threadIdx.x;
    if (i < n4) {
        float4 av = reinterpret_cast<const float4*>(a)[i];
        float4 bv = reinterpret_cast<const float4*>(b)[i];
        float4 cv;
        cv.x = av.x + bv.x; cv.y = av.y + bv.y; cv.z = av.z + bv.z; cv.w = av.w + bv.w;
        reinterpret_cast<float4*>(c)[i] = cv;
    }
}

// ---------------- softmax over 16 per (l,h), in-place ----------------
__global__ void softmax16_kernel(float* __restrict__ a) {
    int idx = blockIdx.x * blockDim.x + threadIdx.x;
    if (idx >= L_TOT * NH) return;
    float4* p = reinterpret_cast<float4*>(a + (size_t)idx * 16);
    float4 v[4];
    #pragma unroll
    for (int i = 0; i < 4; i++) v[i] = p[i];
    float m = -1e30f;
    #pragma unroll
    for (int i = 0; i < 4; i++)
        m = fmaxf(m, fmaxf(fmaxf(v[i].x, v[i].y), fmaxf(v[i].z, v[i].w)));
    float s = 0.f;
    #pragma unroll
    for (int i = 0; i < 4; i++) {
        v[i].x = __expf(v[i].x - m); v[i].y = __expf(v[i].y - m);
        v[i].z = __expf(v[i].z - m); v[i].w = __expf(v[i].w - m);
        s += v[i].x + v[i].y + v[i].z + v[i].w;
    }
    float inv = 1.f / s;
    #pragma unroll
    for (int i = 0; i < 4; i++) {
        v[i].x *= inv; v[i].y *= inv; v[i].z *= inv; v[i].w *= inv;
        p[i] = v[i];
    }
}

// ---------------- multi-scale deformable attention core ----------------
__global__ void msda_kernel(const float* __restrict__ value,
                            const float* __restrict__ off,
                            const float* __restrict__ attn,
                            const float* __restrict__ refpts,
                            float* __restrict__ out) {
    const int warp_in_block = threadIdx.x >> 5;
    const int lane = threadIdx.x & 31;
    const int l = blockIdx.x;
    const int h = warp_in_block;
    if (l >= L_TOT) return;

    const int Hs[4] = {80, 40, 20, 10};
    const int Ws[4] = {80, 40, 20, 10};
    const int starts[4] = {0, 6400, 8000, 8400};

    float acc = 0.f;
    #pragma unroll
    for (int lvl = 0; lvl < NL; ++lvl) {
        const int Wl = Ws[lvl], Hl = Hs[lvl], st = starts[lvl];
        const float rx = refpts[((size_t)l * NL + lvl) * 2 + 0];
        const float ry = refpts[((size_t)l * NL + lvl) * 2 + 1];
        #pragma unroll
        for (int p = 0; p < NP; ++p) {
            const size_t oi = (size_t)l * DD + h * (NL * NP * 2) + lvl * (NP * 2) + p * 2;
            const float x = rx * Wl + off[oi] - 0.5f;
            const float y = ry * Hl + off[oi + 1] - 0.5f;
            const float aw = attn[(size_t)l * 128 + h * 16 + lvl * 4 + p];
            const int x0 = (int)floorf(x);
            const int y0 = (int)floorf(y);
            const float fx = x - x0;
            const float fy = y - y0;
            float samp = 0.f;
            #pragma unroll
            for (int dy = 0; dy < 2; ++dy) {
                #pragma unroll
                for (int dx = 0; dx < 2; ++dx) {
                    const int xi = x0 + dx;
                    const int yi = y0 + dy;
                    if (xi >= 0 && xi < Wl && yi >= 0 && yi < Hl) {
                        const float w = (dx ? fx : 1.f - fx) * (dy ? fy : 1.f - fy);
                        const size_t vidx = (size_t)(st + yi * Wl + xi) * DD + h * DH + lane;
                        samp = fmaf(w, value[vidx], samp);
                    }
                }
            }
            acc = fmaf(aw, samp, acc);
        }
    }
    out[(size_t)l * DD + h * DH + lane] = acc;
}

// ---------------- fused residual add + LayerNorm ----------------
__global__ void add_ln_kernel(const float* __restrict__ a, const float* __restrict__ b,
                              const float* __restrict__ g, const float* __restrict__ be,
                              float* __restrict__ out) {
    const int row = blockIdx.x;
    const int t = threadIdx.x;
    const float v = a[(size_t)row * DD + t] + b[(size_t)row * DD + t];

    float s = v, s2 = v * v;
    __shared__ float sh[8], sh2[8];
    #pragma unroll
    for (int o = 16; o > 0; o >>= 1) {
        s  += __shfl_down_sync(0xffffffffu, s, o);
        s2 += __shfl_down_sync(0xffffffffu, s2, o);
    }
    const int w = t >> 5, lane = t & 31;
    if (lane == 0) { sh[w] = s; sh2[w] = s2; }
    __syncthreads();
    if (w == 0) {
        s  = (lane < 8) ? sh[lane]  : 0.f;
        s2 = (lane < 8) ? sh2[lane] : 0.f;
        #pragma unroll
        for (int o = 4; o > 0; o >>= 1) {
            s  += __shfl_down_sync(0xffffffffu, s, o);
            s2 += __shfl_down_sync(0xffffffffu, s2, o);
        }
        if (lane == 0) { sh[0] = s; sh2[0] = s2; }
    }
    __syncthreads();
    const float mean = sh[0] * (1.f / DD);
    const float var  = sh2[0] * (1.f / DD) - mean * mean;
    const float inv  = rsqrtf(var + 1e-5f);
    out[(size_t)row * DD + t] = (v - mean) * inv * g[t] + be[t];
}

// ---------------- launch ----------------
extern "C" void kernel_launch(void* const* d_in, const int* in_sizes, int n_in,
                              void* d_out, int out_size) {
    const float* src  = (const float*)d_in[0];
    const float* pos  = (const float*)d_in[1];
    const float* refp = (const float*)d_in[2];
    const float* Wo   = (const float*)d_in[6];
    const float* bo   = (const float*)d_in[7];
    const float* Wa   = (const float*)d_in[8];
    const float* ba   = (const float*)d_in[9];
    const float* Wv   = (const float*)d_in[10];
    const float* bv   = (const float*)d_in[11];
    const float* Wout = (const float*)d_in[12];
    const float* bout = (const float*)d_in[13];
    const float* W1   = (const float*)d_in[14];
    const float* b1   = (const float*)d_in[15];
    const float* W2   = (const float*)d_in[16];
    const float* b2   = (const float*)d_in[17];
    const float* g1   = (const float*)d_in[18];
    const float* be1  = (const float*)d_in[19];
    const float* g2   = (const float*)d_in[20];
    const float* be2  = (const float*)d_in[21];
    float* out = (float*)d_out;

    float *q, *off, *attn, *value, *attnout, *x1, *h, *tmp;
    float *WoT, *WaT, *WvT, *WoutT, *W1T, *W2T;
    cudaGetSymbolAddress((void**)&q,       g_q);
    cudaGetSymbolAddress((void**)&off,     g_off);
    cudaGetSymbolAddress((void**)&attn,    g_attn);
    cudaGetSymbolAddress((void**)&value,   g_value);
    cudaGetSymbolAddress((void**)&attnout, g_attnout);
    cudaGetSymbolAddress((void**)&x1,      g_x1);
    cudaGetSymbolAddress((void**)&h,       g_h);
    cudaGetSymbolAddress((void**)&tmp,     g_tmp);
    cudaGetSymbolAddress((void**)&WoT,     g_WoT);
    cudaGetSymbolAddress((void**)&WaT,     g_WaT);
    cudaGetSymbolAddress((void**)&WvT,     g_WvT);
    cudaGetSymbolAddress((void**)&WoutT,   g_WoutT);
    cudaGetSymbolAddress((void**)&W1T,     g_W1T);
    cudaGetSymbolAddress((void**)&W2T,     g_W2T);

    static int smem_set = 0;
    if (!smem_set) {
        cudaFuncSetAttribute(gemm_tf32_kernel,
                             cudaFuncAttributeMaxDynamicSharedMemorySize, GEMM_SMEM_BYTES);
        smem_set = 1;
    }

    const int M = L_TOT;
    const dim3 blk(256);
    const dim3 tblk(32, 8);
    const int MT = (M + 127) / 128;  // 67

    transpose_kernel<<<dim3(256 / 32, 256 / 32), tblk>>>(Wo,   WoT,   256, 256);
    transpose_kernel<<<dim3(128 / 32, 256 / 32), tblk>>>(Wa,   WaT,   256, 128);
    transpose_kernel<<<dim3(256 / 32, 256 / 32), tblk>>>(Wv,   WvT,   256, 256);
    transpose_kernel<<<dim3(256 / 32, 256 / 32), tblk>>>(Wout, WoutT, 256, 256);
    transpose_kernel<<<dim3(1024 / 32, 256 / 32), tblk>>>(W1,  W1T,   256, 1024);
    transpose_kernel<<<dim3(256 / 32, 1024 / 32), tblk>>>(W2,  W2T,   1024, 256);

    // 1) q = src + pos
    add_kernel<<<(M * DD / 4 + 255) / 256, blk>>>(src, pos, q, M * DD / 4);

    // 2) off = q @ Wo + bo
    gemm_tf32_kernel<<<dim3(2, MT), 256, GEMM_SMEM_BYTES>>>(q, WoT, bo, off, M, 256, 256, 0);

    // 3) attn logits = q @ Wa + ba
    gemm_tf32_kernel<<<dim3(1, MT), 256, GEMM_SMEM_BYTES>>>(q, WaT, ba, attn, M, 128, 256, 0);

    // 4) softmax over 16 per (l,h)
    softmax16_kernel<<<(M * NH + 255) / 256, blk>>>(attn);

    // 5) value = src @ Wv + bv
    gemm_tf32_kernel<<<dim3(2, MT), 256, GEMM_SMEM_BYTES>>>(src, WvT, bv, value, M, 256, 256, 0);

    // 6) deformable attention sampling
    msda_kernel<<<M, blk>>>(value, off, attn, refp, attnout);

    // 7) src2 = attnout @ Wout + bout
    gemm_tf32_kernel<<<dim3(2, MT), 256, GEMM_SMEM_BYTES>>>(attnout, WoutT, bout, tmp, M, 256, 256, 0);

    // 8) x1 = LN(src + src2)
    add_ln_kernel<<<M, blk>>>(src, tmp, g1, be1, x1);

    // 9) h = relu(x1 @ W1 + b1)
    gemm_tf32_kernel<<<dim3(8, MT), 256, GEMM_SMEM_BYTES>>>(x1, W1T, b1, h, M, 1024, 256, 1);

    // 10) tmp = h @ W2 + b2
    gemm_tf32_kernel<<<dim3(2, MT), 256, GEMM_SMEM_BYTES>>>(h, W2T, b2, tmp, M, 256, 1024, 0);

    // 11) out = LN(x1 + tmp)
    add_ln_kernel<<<M, blk>>>(x1, tmp, g2, be2, out);
}

// round 4
// speedup vs baseline: 2.3448x; 1.1203x over previous
#include <cuda_runtime.h>
#include <math.h>
#include <stdint.h>

#define L_TOT 8500
#define DD 256
#define NH 8
#define NL 4
#define NP 4
#define DH 32
#define DFF 1024

// ---------------- scratch ----------------
__device__ float g_q[L_TOT * DD];
__device__ float g_off[L_TOT * DD];
__device__ float g_attn[L_TOT * 128];
__device__ float g_value[L_TOT * DD];
__device__ float g_attnout[L_TOT * DD];
__device__ float g_x1[L_TOT * DD];
__device__ float g_h[L_TOT * DFF];
__device__ float g_tmp[L_TOT * DD];

// ---------------- helpers ----------------
__device__ __forceinline__ uint32_t smem_u32(const void* p) {
    uint32_t a;
    asm("{ .reg .u64 t; cvta.to.shared.u64 t, %1; cvt.u32.u64 %0, t; }" : "=r"(a) : "l"(p));
    return a;
}
__device__ __forceinline__ uint32_t f2tf32(float x) {
    uint32_t r;
    asm("cvt.rna.tf32.f32 %0, %1;" : "=r"(r) : "f"(x));
    return r;
}
__device__ __forceinline__ void cp_async16(uint32_t sa, const void* ga) {
    asm volatile("cp.async.cg.shared.global [%0], [%1], 16;" :: "r"(sa), "l"(ga));
}
__device__ __forceinline__ void cp_commit() {
    asm volatile("cp.async.commit_group;" ::: "memory");
}
template <int N_>
__device__ __forceinline__ void cp_wait() {
    asm volatile("cp.async.wait_group %0;" :: "n"(N_) : "memory");
}
__device__ __forceinline__ void mma_tf32(float* c, const uint32_t* a, const uint32_t* b) {
    asm volatile(
        "mma.sync.aligned.m16n8k8.row.col.f32.tf32.tf32.f32 "
        "{%0,%1,%2,%3}, {%4,%5,%6,%7}, {%8,%9}, {%0,%1,%2,%3};"
        : "+f"(c[0]), "+f"(c[1]), "+f"(c[2]), "+f"(c[3])
        : "r"(a[0]), "r"(a[1]), "r"(a[2]), "r"(a[3]), "r"(b[0]), "r"(b[1]));
}

// ---------------- tf32 tensor-core GEMM (mma.sync, no weight transpose) ----
// C[M,N] = A[M,K] @ W[K,N] + bias.  Block tile 128x128, BK=32, 3-stage
// cp.async pipeline, 256 threads = 8 warps (2x4), warp tile 64x32.
// A tile SMEM: [128 m][stride 36], B tile SMEM: [32 k][stride 136].
#define SA 36
#define SB 136
#define A_TILE (128 * SA)                 // 4608 floats
#define B_TILE (32 * SB)                  // 4352 floats
#define STAGES 3
#define GEMM_SMEM_BYTES (STAGES * (A_TILE + B_TILE) * 4)   // 107520 B

__global__ void __launch_bounds__(256) gemm_tf32_kernel(
    const float* __restrict__ A, const float* __restrict__ W,
    const float* __restrict__ bias, float* __restrict__ C,
    int M, int N, int K, int relu)
{
    extern __shared__ float sm[];
    float* AsBase = sm;                       // [STAGES][A_TILE]
    float* BsBase = sm + STAGES * A_TILE;     // [STAGES][B_TILE]
    const uint32_t smem_base = smem_u32(sm);
    const uint32_t bsmem_base = smem_base + STAGES * A_TILE * 4;

    const int tid = threadIdx.x;
    const int wid = tid >> 5;
    const int lane = tid & 31;
    const int warp_m = wid >> 2;        // 0..1
    const int warp_n = wid & 3;         // 0..3
    const int tr = lane >> 2;           // 0..7
    const int tc = lane & 3;            // 0..3
    const int blockRow = blockIdx.y * 128;
    const int blockCol = blockIdx.x * 128;

    float acc[4][4][4];
    #pragma unroll
    for (int i = 0; i < 4; i++)
        #pragma unroll
        for (int j = 0; j < 4; j++)
            #pragma unroll
            for (int r = 0; r < 4; r++) acc[i][j][r] = 0.f;

    // A load mapping: 4 chunks (rows tid>>3 + it*32, col (tid&7)*4)
    const int a_lrow = tid >> 3;
    const int a_lc4 = (tid & 7) * 4;
    // B load mapping: chunk f = tid + it*256; row f>>5 (0..31), col (f&31)*4
    const int NC = K >> 5;

    auto issue_stage = [&](int s, int k0) {
        const uint32_t a_base = smem_base + (uint32_t)(s * A_TILE * 4);
        const uint32_t b_base = bsmem_base + (uint32_t)(s * B_TILE * 4);
        #pragma unroll
        for (int it = 0; it < 4; ++it) {
            const int row = a_lrow + it * 32;
            int gr = blockRow + row;
            gr = gr < M - 1 ? gr : M - 1;
            cp_async16(a_base + (uint32_t)((row * SA + a_lc4) * 4),
                       A + (size_t)gr * K + k0 + a_lc4);
        }
        #pragma unroll
        for (int it = 0; it < 4; ++it) {
            const int f = tid + it * 256;
            const int krow = f >> 5;
            const int c4 = (f & 31) * 4;
            cp_async16(b_base + (uint32_t)((krow * SB + c4) * 4),
                       W + (size_t)(k0 + krow) * N + blockCol + c4);
        }
        cp_commit();
    };

    issue_stage(0, 0);
    issue_stage(1, 32);
    issue_stage(2, 64);

    for (int i = 0; i < NC; ++i) {
        const int s = i % 3;
        cp_wait<2>();
        __syncthreads();

        const float* As = AsBase + s * A_TILE;
        const float* Bs = BsBase + s * B_TILE;
        const int amr = warp_m * 64;
        const int bnr = warp_n * 32;

        #pragma unroll
        for (int kb = 0; kb < 32; kb += 8) {
            uint32_t afr[4][4];
            #pragma unroll
            for (int im = 0; im < 4; ++im) {
                const float* ap = As + (amr + im * 16 + tr) * SA + kb + tc;
                afr[im][0] = f2tf32(ap[0]);
                afr[im][1] = f2tf32(ap[8 * SA]);
                afr[im][2] = f2tf32(ap[4]);
                afr[im][3] = f2tf32(ap[8 * SA + 4]);
            }
            uint32_t bfr[4][2];
            #pragma unroll
            for (int in_ = 0; in_ < 4; ++in_) {
                const float* bp = Bs + (kb + tc) * SB + bnr + in_ * 8 + tr;
                bfr[in_][0] = f2tf32(bp[0]);
                bfr[in_][1] = f2tf32(bp[4 * SB]);
            }
            #pragma unroll
            for (int im = 0; im < 4; ++im)
                #pragma unroll
                for (int in_ = 0; in_ < 4; ++in_)
                    mma_tf32(acc[im][in_], afr[im], bfr[in_]);
        }

        __syncthreads();
        if (i + 3 < NC) issue_stage(s, (i + 3) << 5);
    }

    // epilogue
    #pragma unroll
    for (int im = 0; im < 4; ++im) {
        const int row0 = blockRow + warp_m * 64 + im * 16 + tr;
        #pragma unroll
        for (int in_ = 0; in_ < 4; ++in_) {
            const int col = blockCol + warp_n * 32 + in_ * 8 + 2 * tc;
            const float bx = bias[col], by = bias[col + 1];
            float2 v0 = make_float2(acc[im][in_][0] + bx, acc[im][in_][1] + by);
            float2 v1 = make_float2(acc[im][in_][2] + bx, acc[im][in_][3] + by);
            if (relu) {
                v0.x = fmaxf(v0.x, 0.f); v0.y = fmaxf(v0.y, 0.f);
                v1.x = fmaxf(v1.x, 0.f); v1.y = fmaxf(v1.y, 0.f);
            }
            if (row0 < M)
                *reinterpret_cast<float2*>(C + (size_t)row0 * N + col) = v0;
            if (row0 + 8 < M)
                *reinterpret_cast<float2*>(C + (size_t)(row0 + 8) * N + col) = v1;
        }
    }
}

// ---------------- elementwise add ----------------
__global__ void add_kernel(const float* __restrict__ a, const float* __restrict__ b,
                           float* __restrict__ c, int n4) {
    int i = blockIdx.x * blockDim.x + threadIdx.x;
    if (i < n4) {
        float4 av = reinterpret_cast<const float4*>(a)[i];
        float4 bv = reinterpret_cast<const float4*>(b)[i];
        float4 cv;
        cv.x = av.x + bv.x; cv.y = av.y + bv.y; cv.z = av.z + bv.z; cv.w = av.w + bv.w;
        reinterpret_cast<float4*>(c)[i] = cv;
    }
}

// ---------------- softmax over 16 per (l,h), in-place ----------------
__global__ void softmax16_kernel(float* __restrict__ a) {
    int idx = blockIdx.x * blockDim.x + threadIdx.x;
    if (idx >= L_TOT * NH) return;
    float4* p = reinterpret_cast<float4*>(a + (size_t)idx * 16);
    float4 v[4];
    #pragma unroll
    for (int i = 0; i < 4; i++) v[i] = p[i];
    float m = -1e30f;
    #pragma unroll
    for (int i = 0; i < 4; i++)
        m = fmaxf(m, fmaxf(fmaxf(v[i].x, v[i].y), fmaxf(v[i].z, v[i].w)));
    float s = 0.f;
    #pragma unroll
    for (int i = 0; i < 4; i++) {
        v[i].x = __expf(v[i].x - m); v[i].y = __expf(v[i].y - m);
        v[i].z = __expf(v[i].z - m); v[i].w = __expf(v[i].w - m);
        s += v[i].x + v[i].y + v[i].z + v[i].w;
    }
    float inv = 1.f / s;
    #pragma unroll
    for (int i = 0; i < 4; i++) {
        v[i].x *= inv; v[i].y *= inv; v[i].z *= inv; v[i].w *= inv;
        p[i] = v[i];
    }
}

// ---------------- multi-scale deformable attention core ----------------
__global__ void msda_kernel(const float* __restrict__ value,
                            const float* __restrict__ off,
                            const float* __restrict__ attn,
                            const float* __restrict__ refpts,
                            float* __restrict__ out) {
    const int warp_in_block = threadIdx.x >> 5;
    const int lane = threadIdx.x & 31;
    const int l = blockIdx.x;
    const int h = warp_in_block;
    if (l >= L_TOT) return;

    const int Hs[4] = {80, 40, 20, 10};
    const int Ws[4] = {80, 40, 20, 10};
    const int starts[4] = {0, 6400, 8000, 8400};

    float acc = 0.f;
    #pragma unroll
    for (int lvl = 0; lvl < NL; ++lvl) {
        const int Wl = Ws[lvl], Hl = Hs[lvl], st = starts[lvl];
        const float rx = refpts[((size_t)l * NL + lvl) * 2 + 0];
        const float ry = refpts[((size_t)l * NL + lvl) * 2 + 1];
        #pragma unroll
        for (int p = 0; p < NP; ++p) {
            const size_t oi = (size_t)l * DD + h * (NL * NP * 2) + lvl * (NP * 2) + p * 2;
            const float x = rx * Wl + off[oi] - 0.5f;
            const float y = ry * Hl + off[oi + 1] - 0.5f;
            const float aw = attn[(size_t)l * 128 + h * 16 + lvl * 4 + p];
            const int x0 = (int)floorf(x);
            const int y0 = (int)floorf(y);
            const float fx = x - x0;
            const float fy = y - y0;
            float samp = 0.f;
            #pragma unroll
            for (int dy = 0; dy < 2; ++dy) {
                #pragma unroll
                for (int dx = 0; dx < 2; ++dx) {
                    const int xi = x0 + dx;
                    const int yi = y0 + dy;
                    if (xi >= 0 && xi < Wl && yi >= 0 && yi < Hl) {
                        const float w = (dx ? fx : 1.f - fx) * (dy ? fy : 1.f - fy);
                        const size_t vidx = (size_t)(st + yi * Wl + xi) * DD + h * DH + lane;
                        samp = fmaf(w, value[vidx], samp);
                    }
                }
            }
            acc = fmaf(aw, samp, acc);
        }
    }
    out[(size_t)l * DD + h * DH + lane] = acc;
}

// ---------------- fused residual add + LayerNorm ----------------
__global__ void add_ln_kernel(const float* __restrict__ a, const float* __restrict__ b,
                              const float* __restrict__ g, const float* __restrict__ be,
                              float* __restrict__ out) {
    const int row = blockIdx.x;
    const int t = threadIdx.x;
    const float v = a[(size_t)row * DD + t] + b[(size_t)row * DD + t];

    float s = v, s2 = v * v;
    __shared__ float sh[8], sh2[8];
    #pragma unroll
    for (int o = 16; o > 0; o >>= 1) {
        s  += __shfl_down_sync(0xffffffffu, s, o);
        s2 += __shfl_down_sync(0xffffffffu, s2, o);
    }
    const int w = t >> 5, lane = t & 31;
    if (lane == 0) { sh[w] = s; sh2[w] = s2; }
    __syncthreads();
    if (w == 0) {
        s  = (lane < 8) ? sh[lane]  : 0.f;
        s2 = (lane < 8) ? sh2[lane] : 0.f;
        #pragma unroll
        for (int o = 4; o > 0; o >>= 1) {
            s  += __shfl_down_sync(0xffffffffu, s, o);
            s2 += __shfl_down_sync(0xffffffffu, s2, o);
        }
        if (lane == 0) { sh[0] = s; sh2[0] = s2; }
    }
    __syncthreads();
    const float mean = sh[0] * (1.f / DD);
    const float var  = sh2[0] * (1.f / DD) - mean * mean;
    const float inv  = rsqrtf(var + 1e-5f);
    out[(size_t)row * DD + t] = (v - mean) * inv * g[t] + be[t];
}

// ---------------- launch ----------------
extern "C" void kernel_launch(void* const* d_in, const int* in_sizes, int n_in,
                              void* d_out, int out_size) {
    const float* src  = (const float*)d_in[0];
    const float* pos  = (const float*)d_in[1];
    const float* refp = (const float*)d_in[2];
    const float* Wo   = (const float*)d_in[6];
    const float* bo   = (const float*)d_in[7];
    const float* Wa   = (const float*)d_in[8];
    const float* ba   = (const float*)d_in[9];
    const float* Wv   = (const float*)d_in[10];
    const float* bv   = (const float*)d_in[11];
    const float* Wout = (const float*)d_in[12];
    const float* bout = (const float*)d_in[13];
    const float* W1   = (const float*)d_in[14];
    const float* b1   = (const float*)d_in[15];
    const float* W2   = (const float*)d_in[16];
    const float* b2   = (const float*)d_in[17];
    const float* g1   = (const float*)d_in[18];
    const float* be1  = (const float*)d_in[19];
    const float* g2   = (const float*)d_in[20];
    const float* be2  = (const float*)d_in[21];
    float* out = (float*)d_out;

    float *q, *off, *attn, *value, *attnout, *x1, *h, *tmp;
    cudaGetSymbolAddress((void**)&q,       g_q);
    cudaGetSymbolAddress((void**)&off,     g_off);
    cudaGetSymbolAddress((void**)&attn,    g_attn);
    cudaGetSymbolAddress((void**)&value,   g_value);
    cudaGetSymbolAddress((void**)&attnout, g_attnout);
    cudaGetSymbolAddress((void**)&x1,      g_x1);
    cudaGetSymbolAddress((void**)&h,       g_h);
    cudaGetSymbolAddress((void**)&tmp,     g_tmp);

    static int smem_set = 0;
    if (!smem_set) {
        cudaFuncSetAttribute(gemm_tf32_kernel,
                             cudaFuncAttributeMaxDynamicSharedMemorySize, GEMM_SMEM_BYTES);
        smem_set = 1;
    }

    const int M = L_TOT;
    const dim3 blk(256);
    const int MT = (M + 127) / 128;  // 67

    // 1) q = src + pos
    add_kernel<<<(M * DD / 4 + 255) / 256, blk>>>(src, pos, q, M * DD / 4);

    // 2) off = q @ Wo + bo
    gemm_tf32_kernel<<<dim3(2, MT), 256, GEMM_SMEM_BYTES>>>(q, Wo, bo, off, M, 256, 256, 0);

    // 3) attn logits = q @ Wa + ba
    gemm_tf32_kernel<<<dim3(1, MT), 256, GEMM_SMEM_BYTES>>>(q, Wa, ba, attn, M, 128, 256, 0);

    // 4) softmax over 16 per (l,h)
    softmax16_kernel<<<(M * NH + 255) / 256, blk>>>(attn);

    // 5) value = src @ Wv + bv
    gemm_tf32_kernel<<<dim3(2, MT), 256, GEMM_SMEM_BYTES>>>(src, Wv, bv, value, M, 256, 256, 0);

    // 6) deformable attention sampling
    msda_kernel<<<M, blk>>>(value, off, attn, refp, attnout);

    // 7) src2 = attnout @ Wout + bout
    gemm_tf32_kernel<<<dim3(2, MT), 256, GEMM_SMEM_BYTES>>>(attnout, Wout, bout, tmp, M, 256, 256, 0);

    // 8) x1 = LN(src + src2)
    add_ln_kernel<<<M, blk>>>(src, tmp, g1, be1, x1);

    // 9) h = relu(x1 @ W1 + b1)
    gemm_tf32_kernel<<<dim3(8, MT), 256, GEMM_SMEM_BYTES>>>(x1, W1, b1, h, M, 1024, 256, 1);

    // 10) tmp = h @ W2 + b2
    gemm_tf32_kernel<<<dim3(2, MT), 256, GEMM_SMEM_BYTES>>>(h, W2, b2, tmp, M, 256, 1024, 0);

    // 11) out = LN(x1 + tmp)
    add_ln_kernel<<<M, blk>>>(x1, tmp, g2, be2, out);
}

// round 5
// speedup vs baseline: 3.0321x; 1.2931x over previous
#include <cuda_runtime.h>
#include <cuda_bf16.h>
#include <math.h>
#include <stdint.h>

#define L_TOT 8500
#define DD 256
#define NH 8
#define NL 4
#define NP 4
#define DH 32
#define DFF 1024

// ---------------- fp32 scratch ----------------
__device__ float g_off[L_TOT * DD];
__device__ float g_attn[L_TOT * 128];
__device__ float g_value[L_TOT * DD];
__device__ float g_x1[L_TOT * DD];
__device__ float g_tmp[L_TOT * DD];
// ---------------- bf16 scratch ----------------
__device__ __nv_bfloat16 g_qbf[L_TOT * DD];
__device__ __nv_bfloat16 g_srcbf[L_TOT * DD];
__device__ __nv_bfloat16 g_aobf[L_TOT * DD];
__device__ __nv_bfloat16 g_x1bf[L_TOT * DD];
__device__ __nv_bfloat16 g_hbf[L_TOT * DFF];
// weights bf16: Wo@0 Wa@65536 Wv@98304 Wout@163840 W1@229376 W2@491520
#define WOFF_O 0
#define WOFF_A 65536
#define WOFF_V 98304
#define WOFF_OUT 163840
#define WOFF_1 229376
#define WOFF_2 491520
#define WTOTAL 753664
__device__ __nv_bfloat16 g_wbf[WTOTAL];

// ---------------- helpers ----------------
__device__ __forceinline__ uint32_t smem_u32(const void* p) {
    uint32_t a;
    asm("{ .reg .u64 t; cvta.to.shared.u64 t, %1; cvt.u32.u64 %0, t; }" : "=r"(a) : "l"(p));
    return a;
}
__device__ __forceinline__ void cp_async16(uint32_t sa, const void* ga) {
    asm volatile("cp.async.cg.shared.global [%0], [%1], 16;" :: "r"(sa), "l"(ga));
}
__device__ __forceinline__ void cp_commit() {
    asm volatile("cp.async.commit_group;" ::: "memory");
}
template <int N_>
__device__ __forceinline__ void cp_wait() {
    asm volatile("cp.async.wait_group %0;" :: "n"(N_) : "memory");
}
__device__ __forceinline__ void mma_bf16(float* c, const uint32_t* a, const uint32_t* b) {
    asm volatile(
        "mma.sync.aligned.m16n8k16.row.col.f32.bf16.bf16.f32 "
        "{%0,%1,%2,%3}, {%4,%5,%6,%7}, {%8,%9}, {%0,%1,%2,%3};"
        : "+f"(c[0]), "+f"(c[1]), "+f"(c[2]), "+f"(c[3])
        : "r"(a[0]), "r"(a[1]), "r"(a[2]), "r"(a[3]), "r"(b[0]), "r"(b[1]));
}
#define LDSM_X4(r0, r1, r2, r3, addr) \
    asm volatile("ldmatrix.sync.aligned.m8n8.x4.shared.b16 {%0,%1,%2,%3}, [%4];" \
        : "=r"(r0), "=r"(r1), "=r"(r2), "=r"(r3) : "r"(addr))
#define LDSM_X4_T(r0, r1, r2, r3, addr) \
    asm volatile("ldmatrix.sync.aligned.m8n8.x4.trans.shared.b16 {%0,%1,%2,%3}, [%4];" \
        : "=r"(r0), "=r"(r1), "=r"(r2), "=r"(r3) : "r"(addr))

// ---------------- bf16 tensor-core GEMM ----------------
// block tile 128x128, BK=32, 3 stages, 256 threads = 8 warps (2x4),
// warp tile 64x32.  A SMEM [128 m][40 bf16] (80B rows), B SMEM [32 k][136 bf16].
#define A_TILE_B 10240   // 128*40*2
#define B_TILE_B 8704    // 32*136*2
#define STAGES 3
#define GEMM_SMEM_BYTES (STAGES * (A_TILE_B + B_TILE_B))   // 56832

__device__ __forceinline__ void gemm_body(
    char* sm, const __nv_bfloat16* __restrict__ A, const __nv_bfloat16* __restrict__ W,
    const float* __restrict__ bias, float* __restrict__ C32, __nv_bfloat16* __restrict__ C16,
    int M, int N, int K, int relu, int blockRow, int blockCol)
{
    const uint32_t smem_base = smem_u32(sm);
    const uint32_t b_area = smem_base + STAGES * A_TILE_B;

    const int tid = threadIdx.x;
    const int wid = tid >> 5;
    const int lane = tid & 31;
    const int warp_m = wid >> 2;
    const int warp_n = wid & 3;
    const int tr = lane >> 2;
    const int tc = lane & 3;

    float acc[4][4][4];
    #pragma unroll
    for (int i = 0; i < 4; i++)
        #pragma unroll
        for (int j = 0; j < 4; j++)
            #pragma unroll
            for (int r = 0; r < 4; r++) acc[i][j][r] = 0.f;

    const int NC = K >> 5;

    auto issue_stage = [&](int s, int k0) {
        const uint32_t a_base = smem_base + (uint32_t)(s * A_TILE_B);
        const uint32_t b_base = b_area + (uint32_t)(s * B_TILE_B);
        // A: 512 chunks of 16B (8 bf16): chunk c: row c>>2, kc c&3
        #pragma unroll
        for (int it = 0; it < 2; ++it) {
            const int c = tid + it * 256;
            const int row = c >> 2;
            const int kc = c & 3;
            int gr = blockRow + row;
            gr = gr < M - 1 ? gr : M - 1;
            cp_async16(a_base + (uint32_t)(row * 80 + kc * 16),
                       A + (size_t)gr * K + k0 + kc * 8);
        }
        // B: 512 chunks: chunk c: krow c>>4, nc c&15
        #pragma unroll
        for (int it = 0; it < 2; ++it) {
            const int c = tid + it * 256;
            const int krow = c >> 4;
            const int nc = c & 15;
            cp_async16(b_base + (uint32_t)(krow * 272 + nc * 16),
                       W + (size_t)(k0 + krow) * N + blockCol + nc * 8);
        }
        cp_commit();
    };

    issue_stage(0, 0);
    issue_stage(1, 32);
    issue_stage(2, 64);

    const int amr = warp_m * 64;
    const int bnr = warp_n * 32;
    const int a_row_sel = lane & 15;           // ldmatrix row within 16
    const int a_k_sel = (lane >> 4) << 3;      // 0 or 8

    for (int i = 0; i < NC; ++i) {
        const int s = i % 3;
        cp_wait<2>();
        __syncthreads();

        const uint32_t a_base = smem_base + (uint32_t)(s * A_TILE_B);
        const uint32_t b_base = b_area + (uint32_t)(s * B_TILE_B);

        #pragma unroll
        for (int kb = 0; kb < 32; kb += 16) {
            uint32_t af[4][4];
            #pragma unroll
            for (int im = 0; im < 4; ++im) {
                const uint32_t addr = a_base +
                    (uint32_t)(((amr + im * 16 + a_row_sel) * 40 + kb + a_k_sel) * 2);
                LDSM_X4(af[im][0], af[im][1], af[im][2], af[im][3], addr);
            }
            uint32_t bf[2][4];
            #pragma unroll
            for (int in2 = 0; in2 < 2; ++in2) {
                const uint32_t addr = b_base +
                    (uint32_t)(((kb + a_row_sel) * 136 + bnr + in2 * 16 + a_k_sel) * 2);
                LDSM_X4_T(bf[in2][0], bf[in2][1], bf[in2][2], bf[in2][3], addr);
            }
            #pragma unroll
            for (int im = 0; im < 4; ++im)
                #pragma unroll
                for (int in_ = 0; in_ < 4; ++in_)
                    mma_bf16(acc[im][in_], af[im], &bf[in_ >> 1][(in_ & 1) * 2]);
        }

        __syncthreads();
        if (i + 3 < NC) issue_stage(s, (i + 3) << 5);
    }

    // epilogue
    #pragma unroll
    for (int im = 0; im < 4; ++im) {
        const int row0 = blockRow + warp_m * 64 + im * 16 + tr;
        #pragma unroll
        for (int in_ = 0; in_ < 4; ++in_) {
            const int col = blockCol + warp_n * 32 + in_ * 8 + 2 * tc;
            const float bx = bias[col], by = bias[col + 1];
            float2 v0 = make_float2(acc[im][in_][0] + bx, acc[im][in_][1] + by);
            float2 v1 = make_float2(acc[im][in_][2] + bx, acc[im][in_][3] + by);
            if (relu) {
                v0.x = fmaxf(v0.x, 0.f); v0.y = fmaxf(v0.y, 0.f);
                v1.x = fmaxf(v1.x, 0.f); v1.y = fmaxf(v1.y, 0.f);
            }
            if (C32) {
                if (row0 < M)
                    *reinterpret_cast<float2*>(C32 + (size_t)row0 * N + col) = v0;
                if (row0 + 8 < M)
                    *reinterpret_cast<float2*>(C32 + (size_t)(row0 + 8) * N + col) = v1;
            }
            if (C16) {
                if (row0 < M) {
                    __nv_bfloat162 h0(__float2bfloat16_rn(v0.x), __float2bfloat16_rn(v0.y));
                    *reinterpret_cast<__nv_bfloat162*>(C16 + (size_t)row0 * N + col) = h0;
                }
                if (row0 + 8 < M) {
                    __nv_bfloat162 h1(__float2bfloat16_rn(v1.x), __float2bfloat16_rn(v1.y));
                    *reinterpret_cast<__nv_bfloat162*>(C16 + (size_t)(row0 + 8) * N + col) = h1;
                }
            }
        }
    }
}

__global__ void __launch_bounds__(256) gemm_std_kernel(
    const __nv_bfloat16* A, const __nv_bfloat16* W, const float* bias,
    float* C32, __nv_bfloat16* C16, int M, int N, int K, int relu)
{
    extern __shared__ char sm[];
    gemm_body(sm, A, W, bias, C32, C16, M, N, K, relu,
              blockIdx.y * 128, blockIdx.x * 128);
}

// merged Wo/Wa projection: tiles x=0,1 -> Wo (N=256) -> off; x=2 -> Wa (N=128) -> attn
__global__ void __launch_bounds__(256) gemm_qproj_kernel(
    const __nv_bfloat16* A, const __nv_bfloat16* wbf,
    const float* bo, const float* ba, float* off, float* attn, int M)
{
    extern __shared__ char sm[];
    if (blockIdx.x < 2)
        gemm_body(sm, A, wbf + WOFF_O, bo, off, nullptr, M, 256, 256, 0,
                  blockIdx.y * 128, blockIdx.x * 128);
    else
        gemm_body(sm, A, wbf + WOFF_A, ba, attn, nullptr, M, 128, 256, 0,
                  blockIdx.y * 128, 0);
}

// ---------------- prep: q_bf = bf16(src+pos), src_bf = bf16(src) ------------
__global__ void prep_kernel(const float* __restrict__ src, const float* __restrict__ pos,
                            __nv_bfloat16* __restrict__ qbf, __nv_bfloat16* __restrict__ srcbf,
                            int n4) {
    int i = blockIdx.x * blockDim.x + threadIdx.x;
    if (i >= n4) return;
    float4 s = reinterpret_cast<const float4*>(src)[i];
    float4 p = reinterpret_cast<const float4*>(pos)[i];
    __nv_bfloat162 q0(__float2bfloat16_rn(s.x + p.x), __float2bfloat16_rn(s.y + p.y));
    __nv_bfloat162 q1(__float2bfloat16_rn(s.z + p.z), __float2bfloat16_rn(s.w + p.w));
    __nv_bfloat162 s0(__float2bfloat16_rn(s.x), __float2bfloat16_rn(s.y));
    __nv_bfloat162 s1(__float2bfloat16_rn(s.z), __float2bfloat16_rn(s.w));
    reinterpret_cast<__nv_bfloat162*>(qbf)[i * 2] = q0;
    reinterpret_cast<__nv_bfloat162*>(qbf)[i * 2 + 1] = q1;
    reinterpret_cast<__nv_bfloat162*>(srcbf)[i * 2] = s0;
    reinterpret_cast<__nv_bfloat162*>(srcbf)[i * 2 + 1] = s1;
}

// ---------------- weight conversion fp32 -> bf16 ----------------
__global__ void convw_kernel(const float* w0, const float* w1, const float* w2,
                             const float* w3, const float* w4, const float* w5,
                             __nv_bfloat16* dst) {
    int i4 = blockIdx.x * blockDim.x + threadIdx.x;   // float4 index
    int idx = i4 * 4;
    if (idx >= WTOTAL) return;
    const float* src;
    int off;
    if (idx < WOFF_A)        { src = w0; off = 0; }
    else if (idx < WOFF_V)   { src = w1; off = WOFF_A; }
    else if (idx < WOFF_OUT) { src = w2; off = WOFF_V; }
    else if (idx < WOFF_1)   { src = w3; off = WOFF_OUT; }
    else if (idx < WOFF_2)   { src = w4; off = WOFF_1; }
    else                     { src = w5; off = WOFF_2; }
    float4 v = *reinterpret_cast<const float4*>(src + (idx - off));
    __nv_bfloat162 h0(__float2bfloat16_rn(v.x), __float2bfloat16_rn(v.y));
    __nv_bfloat162 h1(__float2bfloat16_rn(v.z), __float2bfloat16_rn(v.w));
    reinterpret_cast<__nv_bfloat162*>(dst)[i4 * 2] = h0;
    reinterpret_cast<__nv_bfloat162*>(dst)[i4 * 2 + 1] = h1;
}

// ---------------- msda with fused softmax, bf16 output ----------------
__global__ void msda_kernel(const float* __restrict__ value,
                            const float* __restrict__ off,
                            const float* __restrict__ logits,
                            const float* __restrict__ refpts,
                            __nv_bfloat16* __restrict__ out) {
    const int h = threadIdx.x >> 5;
    const int lane = threadIdx.x & 31;
    const int l = blockIdx.x;
    if (l >= L_TOT) return;

    // fused softmax over 16 logits per (l,h), duplicated across both 16-lane halves
    float v = logits[(size_t)l * 128 + h * 16 + (lane & 15)];
    float m = v;
    #pragma unroll
    for (int o = 8; o > 0; o >>= 1) m = fmaxf(m, __shfl_xor_sync(0xffffffffu, m, o));
    float e = __expf(v - m);
    float sum = e;
    #pragma unroll
    for (int o = 8; o > 0; o >>= 1) sum += __shfl_xor_sync(0xffffffffu, sum, o);
    const float w16 = e / sum;

    const int Hs[4] = {80, 40, 20, 10};
    const int Ws[4] = {80, 40, 20, 10};
    const int starts[4] = {0, 6400, 8000, 8400};

    float acc = 0.f;
    #pragma unroll
    for (int lvl = 0; lvl < NL; ++lvl) {
        const int Wl = Ws[lvl], Hl = Hs[lvl], st = starts[lvl];
        const float rx = refpts[((size_t)l * NL + lvl) * 2 + 0];
        const float ry = refpts[((size_t)l * NL + lvl) * 2 + 1];
        #pragma unroll
        for (int p = 0; p < NP; ++p) {
            const size_t oi = (size_t)l * DD + h * (NL * NP * 2) + lvl * (NP * 2) + p * 2;
            const float x = rx * Wl + off[oi] - 0.5f;
            const float y = ry * Hl + off[oi + 1] - 0.5f;
            const float aw = __shfl_sync(0xffffffffu, w16, lvl * 4 + p, 16);
            const int x0 = (int)floorf(x);
            const int y0 = (int)floorf(y);
            const float fx = x - x0;
            const float fy = y - y0;
            float samp = 0.f;
            #pragma unroll
            for (int dy = 0; dy < 2; ++dy) {
                #pragma unroll
                for (int dx = 0; dx < 2; ++dx) {
                    const int xi = x0 + dx;
                    const int yi = y0 + dy;
                    if (xi >= 0 && xi < Wl && yi >= 0 && yi < Hl) {
                        const float w = (dx ? fx : 1.f - fx) * (dy ? fy : 1.f - fy);
                        const size_t vidx = (size_t)(st + yi * Wl + xi) * DD + h * DH + lane;
                        samp = fmaf(w, value[vidx], samp);
                    }
                }
            }
            acc = fmaf(aw, samp, acc);
        }
    }
    out[(size_t)l * DD + h * DH + lane] = __float2bfloat16_rn(acc);
}

// ---------------- fused residual add + LayerNorm (+ optional bf16 copy) ----
__global__ void add_ln_kernel(const float* __restrict__ a, const float* __restrict__ b,
                              const float* __restrict__ g, const float* __restrict__ be,
                              float* __restrict__ out, __nv_bfloat16* __restrict__ out_bf) {
    const int row = blockIdx.x;
    const int t = threadIdx.x;
    const float v = a[(size_t)row * DD + t] + b[(size_t)row * DD + t];

    float s = v, s2 = v * v;
    __shared__ float sh[8], sh2[8];
    #pragma unroll
    for (int o = 16; o > 0; o >>= 1) {
        s  += __shfl_down_sync(0xffffffffu, s, o);
        s2 += __shfl_down_sync(0xffffffffu, s2, o);
    }
    const int w = t >> 5, lane = t & 31;
    if (lane == 0) { sh[w] = s; sh2[w] = s2; }
    __syncthreads();
    if (w == 0) {
        s  = (lane < 8) ? sh[lane]  : 0.f;
        s2 = (lane < 8) ? sh2[lane] : 0.f;
        #pragma unroll
        for (int o = 4; o > 0; o >>= 1) {
            s  += __shfl_down_sync(0xffffffffu, s, o);
            s2 += __shfl_down_sync(0xffffffffu, s2, o);
        }
        if (lane == 0) { sh[0] = s; sh2[0] = s2; }
    }
    __syncthreads();
    const float mean = sh[0] * (1.f / DD);
    const float var  = sh2[0] * (1.f / DD) - mean * mean;
    const float inv  = rsqrtf(var + 1e-5f);
    const float r = (v - mean) * inv * g[t] + be[t];
    out[(size_t)row * DD + t] = r;
    if (out_bf) out_bf[(size_t)row * DD + t] = __float2bfloat16_rn(r);
}

// ---------------- launch ----------------
extern "C" void kernel_launch(void* const* d_in, const int* in_sizes, int n_in,
                              void* d_out, int out_size) {
    const float* src  = (const float*)d_in[0];
    const float* pos  = (const float*)d_in[1];
    const float* refp = (const float*)d_in[2];
    const float* Wo   = (const float*)d_in[6];
    const float* bo   = (const float*)d_in[7];
    const float* Wa   = (const float*)d_in[8];
    const float* ba   = (const float*)d_in[9];
    const float* Wv   = (const float*)d_in[10];
    const float* bv   = (const float*)d_in[11];
    const float* Wout = (const float*)d_in[12];
    const float* bout = (const float*)d_in[13];
    const float* W1   = (const float*)d_in[14];
    const float* b1   = (const float*)d_in[15];
    const float* W2   = (const float*)d_in[16];
    const float* b2   = (const float*)d_in[17];
    const float* g1   = (const float*)d_in[18];
    const float* be1  = (const float*)d_in[19];
    const float* g2   = (const float*)d_in[20];
    const float* be2  = (const float*)d_in[21];
    float* out = (float*)d_out;

    float *off, *attn, *value, *x1, *tmp;
    __nv_bfloat16 *qbf, *srcbf, *aobf, *x1bf, *hbf, *wbf;
    cudaGetSymbolAddress((void**)&off,   g_off);
    cudaGetSymbolAddress((void**)&attn,  g_attn);
    cudaGetSymbolAddress((void**)&value, g_value);
    cudaGetSymbolAddress((void**)&x1,    g_x1);
    cudaGetSymbolAddress((void**)&tmp,   g_tmp);
    cudaGetSymbolAddress((void**)&qbf,   g_qbf);
    cudaGetSymbolAddress((void**)&srcbf, g_srcbf);
    cudaGetSymbolAddress((void**)&aobf,  g_aobf);
    cudaGetSymbolAddress((void**)&x1bf,  g_x1bf);
    cudaGetSymbolAddress((void**)&hbf,   g_hbf);
    cudaGetSymbolAddress((void**)&wbf,   g_wbf);

    static int smem_set = 0;
    if (!smem_set) {
        cudaFuncSetAttribute(gemm_std_kernel,
                             cudaFuncAttributeMaxDynamicSharedMemorySize, GEMM_SMEM_BYTES);
        cudaFuncSetAttribute(gemm_qproj_kernel,
                             cudaFuncAttributeMaxDynamicSharedMemorySize, GEMM_SMEM_BYTES);
        smem_set = 1;
    }

    const int M = L_TOT;
    const dim3 blk(256);
    const int MT = (M + 127) / 128;  // 67

    // 0) convert weights to bf16
    convw_kernel<<<(WTOTAL / 4 + 255) / 256, blk>>>(Wo, Wa, Wv, Wout, W1, W2, wbf);

    // 1) q_bf = bf16(src+pos), src_bf = bf16(src)
    prep_kernel<<<(M * DD / 4 + 255) / 256, blk>>>(src, pos, qbf, srcbf, M * DD / 4);

    // 2) merged: off = q@Wo+bo ; attn = q@Wa+ba
    gemm_qproj_kernel<<<dim3(3, MT), 256, GEMM_SMEM_BYTES>>>(qbf, wbf, bo, ba, off, attn, M);

    // 3) value = src @ Wv + bv
    gemm_std_kernel<<<dim3(2, MT), 256, GEMM_SMEM_BYTES>>>(
        srcbf, wbf + WOFF_V, bv, value, nullptr, M, 256, 256, 0);

    // 4) deformable attention (fused softmax) -> bf16
    msda_kernel<<<M, blk>>>(value, off, attn, refp, aobf);

    // 5) src2 = attnout @ Wout + bout
    gemm_std_kernel<<<dim3(2, MT), 256, GEMM_SMEM_BYTES>>>(
        aobf, wbf + WOFF_OUT, bout, tmp, nullptr, M, 256, 256, 0);

    // 6) x1 = LN(src + src2) (+ bf16 copy)
    add_ln_kernel<<<M, blk>>>(src, tmp, g1, be1, x1, x1bf);

    // 7) h = relu(x1 @ W1 + b1) -> bf16 only
    gemm_std_kernel<<<dim3(8, MT), 256, GEMM_SMEM_BYTES>>>(
        x1bf, wbf + WOFF_1, b1, nullptr, hbf, M, 1024, 256, 1);

    // 8) tmp = h @ W2 + b2
    gemm_std_kernel<<<dim3(2, MT), 256, GEMM_SMEM_BYTES>>>(
        hbf, wbf + WOFF_2, b2, tmp, nullptr, M, 256, 1024, 0);

    // 9) out = LN(x1 + tmp)
    add_ln_kernel<<<M, blk>>>(x1, tmp, g2, be2, out, nullptr);
}